// round 1
// baseline (speedup 1.0000x reference)
#include <cuda_runtime.h>
#include <cuda_bf16.h>
#include <math.h>

// ---------------------------------------------------------------------------
// Problem constants (B=1, S=4096, DIM=1536, HEADS=12, HEAD_DIM=128)
// ---------------------------------------------------------------------------
#define SEQ    4096
#define DIM    1536
#define NHEADS 12
#define HDIM   128
#define EPS    1e-6f

// Scratch (allocation-free rule: __device__ globals)
__device__ float g_q[SEQ * DIM];
__device__ float g_k[SEQ * DIM];
__device__ float g_v[SEQ * DIM];
__device__ float g_attn[SEQ * DIM];
__device__ float g_trig[SEQ * 64 * 2];   // interleaved cos, sin per (pos, pair)

// ---------------------------------------------------------------------------
// Precompute RoPE cos/sin with double-precision range reduction.
// freqs: [SEQ, 64] fp32 angles. 262144 elements.
// ---------------------------------------------------------------------------
__global__ __launch_bounds__(256) void trig_kernel(const float* __restrict__ freqs) {
    int idx = blockIdx.x * blockDim.x + threadIdx.x;
    if (idx >= SEQ * 64) return;
    double a = (double)freqs[idx];
    double s, c;
    sincos(a, &s, &c);
    g_trig[idx * 2 + 0] = (float)c;
    g_trig[idx * 2 + 1] = (float)s;
}

// ---------------------------------------------------------------------------
// SGEMM: C[M,N] = A[M,K] @ W[N,K]^T + bias[N]
// BM=BN=128, BK=8, 256 threads, each thread 8x8. Shapes divide exactly.
// ---------------------------------------------------------------------------
__global__ __launch_bounds__(256) void sgemm_bias_kernel(
    const float* __restrict__ A, const float* __restrict__ W,
    const float* __restrict__ bias, float* __restrict__ C,
    int M, int N, int K)
{
    __shared__ float As[8][128];
    __shared__ float Ws[8][128];

    const int t  = threadIdx.x;
    const int tx = t & 15;        // 0..15 -> col group
    const int ty = t >> 4;        // 0..15 -> row group
    const int bm = blockIdx.y * 128;
    const int bn = blockIdx.x * 128;

    const int l_row = t >> 1;           // 0..127
    const int l_k   = (t & 1) * 4;      // 0 or 4

    const float* Ap = A + (size_t)(bm + l_row) * K + l_k;
    const float* Wp = W + (size_t)(bn + l_row) * K + l_k;

    float acc[8][8];
#pragma unroll
    for (int i = 0; i < 8; i++)
#pragma unroll
        for (int j = 0; j < 8; j++) acc[i][j] = 0.f;

    for (int k0 = 0; k0 < K; k0 += 8) {
        float4 av = *(const float4*)(Ap + k0);
        float4 wv = *(const float4*)(Wp + k0);
        As[l_k + 0][l_row] = av.x; As[l_k + 1][l_row] = av.y;
        As[l_k + 2][l_row] = av.z; As[l_k + 3][l_row] = av.w;
        Ws[l_k + 0][l_row] = wv.x; Ws[l_k + 1][l_row] = wv.y;
        Ws[l_k + 2][l_row] = wv.z; Ws[l_k + 3][l_row] = wv.w;
        __syncthreads();

#pragma unroll
        for (int kk = 0; kk < 8; kk++) {
            float a[8], b[8];
            *(float4*)(a)     = *(const float4*)&As[kk][ty * 8];
            *(float4*)(a + 4) = *(const float4*)&As[kk][ty * 8 + 4];
            *(float4*)(b)     = *(const float4*)&Ws[kk][tx * 8];
            *(float4*)(b + 4) = *(const float4*)&Ws[kk][tx * 8 + 4];
#pragma unroll
            for (int i = 0; i < 8; i++)
#pragma unroll
                for (int j = 0; j < 8; j++)
                    acc[i][j] = fmaf(a[i], b[j], acc[i][j]);
        }
        __syncthreads();
    }

#pragma unroll
    for (int i = 0; i < 8; i++) {
        int row = bm + ty * 8 + i;
#pragma unroll
        for (int j = 0; j < 8; j += 4) {
            int col = bn + tx * 8 + j;
            float4 o;
            o.x = acc[i][j + 0] + bias[col + 0];
            o.y = acc[i][j + 1] + bias[col + 1];
            o.z = acc[i][j + 2] + bias[col + 2];
            o.w = acc[i][j + 3] + bias[col + 3];
            *(float4*)&C[(size_t)row * N + col] = o;
        }
    }
}

// ---------------------------------------------------------------------------
// Fused RMSNorm (over full 1536) + RoPE (per-head adjacent pairs), in-place.
// One block per sequence position.
// ---------------------------------------------------------------------------
__global__ __launch_bounds__(256) void rmsnorm_rope_kernel(
    float* __restrict__ X, const float* __restrict__ g)
{
    __shared__ float sh[DIM];
    __shared__ float red[8];
    __shared__ float s_r;

    const int s = blockIdx.x;
    const int t = threadIdx.x;
    float* row = X + (size_t)s * DIM;

    float ss = 0.f;
    for (int i = t; i < DIM; i += 256) {
        float v = row[i];
        sh[i] = v;
        ss += v * v;
    }
    // warp reduce
#pragma unroll
    for (int off = 16; off > 0; off >>= 1)
        ss += __shfl_xor_sync(0xFFFFFFFFu, ss, off);
    if ((t & 31) == 0) red[t >> 5] = ss;
    __syncthreads();
    if (t == 0) {
        float tot = 0.f;
#pragma unroll
        for (int w = 0; w < 8; w++) tot += red[w];
        s_r = rsqrtf(tot / (float)DIM + EPS);
    }
    __syncthreads();
    const float r = s_r;

    // 768 pairs, pair p -> features (2p, 2p+1), rope pair index p & 63
    for (int p = t; p < DIM / 2; p += 256) {
        int f0 = 2 * p, f1 = 2 * p + 1;
        int j = p & 63;
        float c  = g_trig[((size_t)s * 64 + j) * 2 + 0];
        float sn = g_trig[((size_t)s * 64 + j) * 2 + 1];
        float v0 = sh[f0] * r * g[f0];
        float v1 = sh[f1] * r * g[f1];
        row[f0] = v0 * c - v1 * sn;
        row[f1] = v0 * sn + v1 * c;
    }
}

// ---------------------------------------------------------------------------
// Flash attention: one block = 64 q rows of one head. 256 threads.
// Tiles of 64 keys; online softmax; O accumulated in registers.
// ---------------------------------------------------------------------------
#define FA_BQ 64
#define FA_BK 64
#define QK_STRIDE 132          // 128 + 4 pad (bank-conflict-free row reads)
#define SS_STRIDE 65

// floats: Qs + Ks + Ss + rowScale + rowL
#define FA_SMEM_FLOATS (FA_BQ*QK_STRIDE + FA_BK*QK_STRIDE + FA_BQ*SS_STRIDE + FA_BQ + FA_BQ)
#define FA_SMEM_BYTES  (FA_SMEM_FLOATS * 4)

__global__ __launch_bounds__(256) void flash_attn_kernel(
    const float* __restrict__ Q, const float* __restrict__ K,
    const float* __restrict__ V, float* __restrict__ O)
{
    extern __shared__ float sm[];
    float* Qs       = sm;                                   // 64*132
    float* Ks       = Qs + FA_BQ * QK_STRIDE;               // 64*132 (reused for V)
    float* Ss       = Ks + FA_BK * QK_STRIDE;               // 64*65
    float* rowScale = Ss + FA_BQ * SS_STRIDE;               // 64
    float* rowL     = rowScale + FA_BQ;                     // 64

    const int h  = blockIdx.y;
    const int qb = blockIdx.x;
    const int t  = threadIdx.x;
    const int tx = t & 15;     // col group
    const int ty = t >> 4;     // row group (rows ty*4 .. ty*4+3)

    const int ld = DIM;
    const float scale = 0.08838834764831845f;  // 1/sqrt(128)

    // Load Q tile [64,128] -> padded smem
    for (int i = t; i < FA_BQ * (HDIM / 4); i += 256) {
        int r  = i >> 5;
        int c4 = (i & 31) * 4;
        float4 v = *(const float4*)&Q[(size_t)(qb * FA_BQ + r) * ld + h * HDIM + c4];
        float* dst = &Qs[r * QK_STRIDE + c4];
        dst[0] = v.x; dst[1] = v.y; dst[2] = v.z; dst[3] = v.w;
    }

    float acc[4][8];
#pragma unroll
    for (int i = 0; i < 4; i++)
#pragma unroll
        for (int j = 0; j < 8; j++) acc[i][j] = 0.f;

    float m_i = -1e30f, l_i = 0.f;   // valid for t < 64 only

    for (int kb = 0; kb < SEQ / FA_BK; kb++) {
        __syncthreads();   // prior iteration's PV reads of Ks/Ss complete

        // Load K tile
        for (int i = t; i < FA_BK * (HDIM / 4); i += 256) {
            int r  = i >> 5;
            int c4 = (i & 31) * 4;
            float4 v = *(const float4*)&K[(size_t)(kb * FA_BK + r) * ld + h * HDIM + c4];
            float* dst = &Ks[r * QK_STRIDE + c4];
            dst[0] = v.x; dst[1] = v.y; dst[2] = v.z; dst[3] = v.w;
        }
        __syncthreads();

        // S = Q @ K^T  (each thread 4x4 of the 64x64 tile)
        float s4[4][4];
#pragma unroll
        for (int i = 0; i < 4; i++)
#pragma unroll
            for (int j = 0; j < 4; j++) s4[i][j] = 0.f;

        for (int k = 0; k < HDIM; k += 4) {
            float4 a[4], b[4];
#pragma unroll
            for (int i = 0; i < 4; i++)
                a[i] = *(const float4*)&Qs[(ty * 4 + i) * QK_STRIDE + k];
#pragma unroll
            for (int j = 0; j < 4; j++)
                b[j] = *(const float4*)&Ks[(tx * 4 + j) * QK_STRIDE + k];
#pragma unroll
            for (int i = 0; i < 4; i++)
#pragma unroll
                for (int j = 0; j < 4; j++) {
                    s4[i][j] = fmaf(a[i].x, b[j].x, s4[i][j]);
                    s4[i][j] = fmaf(a[i].y, b[j].y, s4[i][j]);
                    s4[i][j] = fmaf(a[i].z, b[j].z, s4[i][j]);
                    s4[i][j] = fmaf(a[i].w, b[j].w, s4[i][j]);
                }
        }
#pragma unroll
        for (int i = 0; i < 4; i++)
#pragma unroll
            for (int j = 0; j < 4; j++)
                Ss[(ty * 4 + i) * SS_STRIDE + tx * 4 + j] = s4[i][j] * scale;
        __syncthreads();

        // Load V tile into Ks (Ks free after S-compute) + online softmax (t<64)
        for (int i = t; i < FA_BK * (HDIM / 4); i += 256) {
            int r  = i >> 5;
            int c4 = (i & 31) * 4;
            float4 v = *(const float4*)&V[(size_t)(kb * FA_BK + r) * ld + h * HDIM + c4];
            float* dst = &Ks[r * QK_STRIDE + c4];
            dst[0] = v.x; dst[1] = v.y; dst[2] = v.z; dst[3] = v.w;
        }
        if (t < FA_BQ) {
            float* srow = &Ss[t * SS_STRIDE];
            float mx = m_i;
#pragma unroll 8
            for (int j = 0; j < FA_BK; j++) mx = fmaxf(mx, srow[j]);
            float corr = __expf(m_i - mx);
            float sum = 0.f;
#pragma unroll 8
            for (int j = 0; j < FA_BK; j++) {
                float e = __expf(srow[j] - mx);
                srow[j] = e;
                sum += e;
            }
            l_i = l_i * corr + sum;
            m_i = mx;
            rowScale[t] = corr;
        }
        __syncthreads();

        // Rescale accumulators, then O += P @ V
        float cr[4];
#pragma unroll
        for (int i = 0; i < 4; i++) cr[i] = rowScale[ty * 4 + i];
#pragma unroll
        for (int i = 0; i < 4; i++)
#pragma unroll
            for (int j = 0; j < 8; j++) acc[i][j] *= cr[i];

#pragma unroll 4
        for (int k = 0; k < FA_BK; k++) {
            float p[4];
#pragma unroll
            for (int i = 0; i < 4; i++) p[i] = Ss[(ty * 4 + i) * SS_STRIDE + k];
            float4 v0 = *(const float4*)&Ks[k * QK_STRIDE + tx * 8];
            float4 v1 = *(const float4*)&Ks[k * QK_STRIDE + tx * 8 + 4];
#pragma unroll
            for (int i = 0; i < 4; i++) {
                acc[i][0] = fmaf(p[i], v0.x, acc[i][0]);
                acc[i][1] = fmaf(p[i], v0.y, acc[i][1]);
                acc[i][2] = fmaf(p[i], v0.z, acc[i][2]);
                acc[i][3] = fmaf(p[i], v0.w, acc[i][3]);
                acc[i][4] = fmaf(p[i], v1.x, acc[i][4]);
                acc[i][5] = fmaf(p[i], v1.y, acc[i][5]);
                acc[i][6] = fmaf(p[i], v1.z, acc[i][6]);
                acc[i][7] = fmaf(p[i], v1.w, acc[i][7]);
            }
        }
    }

    if (t < FA_BQ) rowL[t] = l_i;
    __syncthreads();

#pragma unroll
    for (int i = 0; i < 4; i++) {
        int row = qb * FA_BQ + ty * 4 + i;
        float inv = 1.f / rowL[ty * 4 + i];
        float4 o0, o1;
        o0.x = acc[i][0] * inv; o0.y = acc[i][1] * inv;
        o0.z = acc[i][2] * inv; o0.w = acc[i][3] * inv;
        o1.x = acc[i][4] * inv; o1.y = acc[i][5] * inv;
        o1.z = acc[i][6] * inv; o1.w = acc[i][7] * inv;
        float* dst = &O[(size_t)row * ld + h * HDIM + tx * 8];
        *(float4*)(dst)     = o0;
        *(float4*)(dst + 4) = o1;
    }
}

// ---------------------------------------------------------------------------
// Launch
// ---------------------------------------------------------------------------
extern "C" void kernel_launch(void* const* d_in, const int* in_sizes, int n_in,
                              void* d_out, int out_size)
{
    const float* x     = (const float*)d_in[0];
    const float* freqs = (const float*)d_in[1];
    const float* Wq    = (const float*)d_in[2];
    const float* bq    = (const float*)d_in[3];
    const float* Wk    = (const float*)d_in[4];
    const float* bk    = (const float*)d_in[5];
    const float* Wv    = (const float*)d_in[6];
    const float* bv    = (const float*)d_in[7];
    const float* Wo    = (const float*)d_in[8];
    const float* bo    = (const float*)d_in[9];
    const float* gq    = (const float*)d_in[10];
    const float* gk    = (const float*)d_in[11];
    float* out = (float*)d_out;

    float *q, *k, *v, *attn;
    cudaGetSymbolAddress((void**)&q,    g_q);
    cudaGetSymbolAddress((void**)&k,    g_k);
    cudaGetSymbolAddress((void**)&v,    g_v);
    cudaGetSymbolAddress((void**)&attn, g_attn);

    cudaFuncSetAttribute(flash_attn_kernel,
                         cudaFuncAttributeMaxDynamicSharedMemorySize, FA_SMEM_BYTES);

    dim3 gemm_grid(DIM / 128, SEQ / 128);   // (12, 32)

    trig_kernel<<<(SEQ * 64 + 255) / 256, 256>>>(freqs);

    sgemm_bias_kernel<<<gemm_grid, 256>>>(x, Wq, bq, q, SEQ, DIM, DIM);
    sgemm_bias_kernel<<<gemm_grid, 256>>>(x, Wk, bk, k, SEQ, DIM, DIM);
    sgemm_bias_kernel<<<gemm_grid, 256>>>(x, Wv, bv, v, SEQ, DIM, DIM);

    rmsnorm_rope_kernel<<<SEQ, 256>>>(q, gq);
    rmsnorm_rope_kernel<<<SEQ, 256>>>(k, gk);

    flash_attn_kernel<<<dim3(SEQ / FA_BQ, NHEADS), 256, FA_SMEM_BYTES>>>(q, k, v, attn);

    sgemm_bias_kernel<<<gemm_grid, 256>>>(attn, Wo, bo, out, SEQ, DIM, DIM);
}

// round 2
// speedup vs baseline: 4.7012x; 4.7012x over previous
#include <cuda_runtime.h>
#include <cuda_bf16.h>
#include <math.h>

// ---------------------------------------------------------------------------
// Problem constants (B=1, S=4096, DIM=1536, HEADS=12, HEAD_DIM=128)
// ---------------------------------------------------------------------------
#define SEQ    4096
#define DIM    1536
#define NHEADS 12
#define HDIM   128
#define EPS    1e-6f

// Scratch (allocation-free rule: __device__ globals)
__device__ float g_q[SEQ * DIM];
__device__ float g_k[SEQ * DIM];
__device__ float g_v[SEQ * DIM];
__device__ float g_attn[SEQ * DIM];
__device__ float g_trig[SEQ * 64 * 2];   // interleaved cos, sin per (pos, pair)

// ---------------------------------------------------------------------------
// tf32 helpers
// ---------------------------------------------------------------------------
__device__ __forceinline__ float to_tf32(float x) {
    unsigned u;
    asm("cvt.rna.tf32.f32 %0, %1;" : "=r"(u) : "f"(x));
    return __uint_as_float(u);
}
__device__ __forceinline__ unsigned fu(float x) { return __float_as_uint(x); }

// D += A*B, m16n8k8, tf32 inputs, f32 accumulate
__device__ __forceinline__ void mma_tf32(float* d, const unsigned* a,
                                         unsigned b0, unsigned b1) {
    asm volatile(
        "mma.sync.aligned.m16n8k8.row.col.f32.tf32.tf32.f32 "
        "{%0,%1,%2,%3}, {%4,%5,%6,%7}, {%8,%9}, {%0,%1,%2,%3};\n"
        : "+f"(d[0]), "+f"(d[1]), "+f"(d[2]), "+f"(d[3])
        : "r"(a[0]), "r"(a[1]), "r"(a[2]), "r"(a[3]), "r"(b0), "r"(b1));
}

// ---------------------------------------------------------------------------
// Precompute RoPE cos/sin with double-precision range reduction.
// ---------------------------------------------------------------------------
__global__ __launch_bounds__(256) void trig_kernel(const float* __restrict__ freqs) {
    int idx = blockIdx.x * blockDim.x + threadIdx.x;
    if (idx >= SEQ * 64) return;
    double a = (double)freqs[idx];
    double s, c;
    sincos(a, &s, &c);
    g_trig[idx * 2 + 0] = (float)c;
    g_trig[idx * 2 + 1] = (float)s;
}

// ---------------------------------------------------------------------------
// tf32 tensor-core GEMM: C[M,N] = A[M,K] @ W[N,K]^T + bias[N]
// BM=BN=128, BK=16, 256 threads (8 warps as 4m x 2n), warp tile 32x64.
// Double-buffered smem, stride 20 (conflict-free fragment access).
// ---------------------------------------------------------------------------
#define GBK     16
#define GSTRIDE 20

struct GPre { float4 a0, a1, w0, w1; };

__device__ __forceinline__ void g_store_stage(float* as, float* ws,
                                              int lrow, int lc4, const GPre& p) {
    float* d0 = &as[lrow * GSTRIDE + lc4];
    float* d1 = &as[(lrow + 64) * GSTRIDE + lc4];
    *(float4*)d0 = make_float4(to_tf32(p.a0.x), to_tf32(p.a0.y), to_tf32(p.a0.z), to_tf32(p.a0.w));
    *(float4*)d1 = make_float4(to_tf32(p.a1.x), to_tf32(p.a1.y), to_tf32(p.a1.z), to_tf32(p.a1.w));
    float* e0 = &ws[lrow * GSTRIDE + lc4];
    float* e1 = &ws[(lrow + 64) * GSTRIDE + lc4];
    *(float4*)e0 = make_float4(to_tf32(p.w0.x), to_tf32(p.w0.y), to_tf32(p.w0.z), to_tf32(p.w0.w));
    *(float4*)e1 = make_float4(to_tf32(p.w1.x), to_tf32(p.w1.y), to_tf32(p.w1.z), to_tf32(p.w1.w));
}

__global__ __launch_bounds__(256, 2) void gemm_tf32_kernel(
    const float* __restrict__ A, const float* __restrict__ W,
    const float* __restrict__ bias, float* __restrict__ C,
    int M, int N, int K)
{
    __shared__ float As[2][128 * GSTRIDE];
    __shared__ float Ws[2][128 * GSTRIDE];

    const int t    = threadIdx.x;
    const int lane = t & 31;
    const int warp = t >> 5;
    const int wm   = warp >> 1;     // 0..3
    const int wn   = warp & 1;      // 0..1
    const int bm   = blockIdx.y * 128;
    const int bn   = blockIdx.x * 128;

    const int lrow = t >> 2;        // 0..63
    const int lc4  = (t & 3) * 4;   // 0,4,8,12

    const float* Ap = A + (size_t)(bm + lrow) * K + lc4;
    const float* Wp = W + (size_t)(bn + lrow) * K + lc4;
    const size_t rK = (size_t)64 * K;

    float c[2][8][4];
#pragma unroll
    for (int mt = 0; mt < 2; mt++)
#pragma unroll
        for (int nt = 0; nt < 8; nt++)
#pragma unroll
            for (int j = 0; j < 4; j++) c[mt][nt][j] = 0.f;

    const int KITERS = K / GBK;   // 96

    GPre p;
    p.a0 = *(const float4*)(Ap);
    p.a1 = *(const float4*)(Ap + rK);
    p.w0 = *(const float4*)(Wp);
    p.w1 = *(const float4*)(Wp + rK);
    g_store_stage(As[0], Ws[0], lrow, lc4, p);
    __syncthreads();

    const int r_a  = wm * 32 + (lane >> 2);   // warp A row base
    const int r_b  = wn * 64 + (lane >> 2);   // warp B row base
    const int kq   = lane & 3;

    for (int it = 0; it < KITERS; ++it) {
        const int cur = it & 1;
        if (it + 1 < KITERS) {
            const float* ap = Ap + (it + 1) * GBK;
            const float* wp = Wp + (it + 1) * GBK;
            p.a0 = *(const float4*)(ap);
            p.a1 = *(const float4*)(ap + rK);
            p.w0 = *(const float4*)(wp);
            p.w1 = *(const float4*)(wp + rK);
        }

        const float* as = As[cur];
        const float* ws = Ws[cur];
#pragma unroll
        for (int kt = 0; kt < 2; ++kt) {
            const int kc = kt * 8 + kq;
            unsigned a[2][4];
#pragma unroll
            for (int mt = 0; mt < 2; ++mt) {
                int r = r_a + mt * 16;
                a[mt][0] = fu(as[r * GSTRIDE + kc]);
                a[mt][1] = fu(as[(r + 8) * GSTRIDE + kc]);
                a[mt][2] = fu(as[r * GSTRIDE + kc + 4]);
                a[mt][3] = fu(as[(r + 8) * GSTRIDE + kc + 4]);
            }
#pragma unroll
            for (int nt = 0; nt < 8; ++nt) {
                int n = r_b + nt * 8;
                unsigned b0 = fu(ws[n * GSTRIDE + kc]);
                unsigned b1 = fu(ws[n * GSTRIDE + kc + 4]);
                mma_tf32(c[0][nt], a[0], b0, b1);
                mma_tf32(c[1][nt], a[1], b0, b1);
            }
        }

        if (it + 1 < KITERS) g_store_stage(As[cur ^ 1], Ws[cur ^ 1], lrow, lc4, p);
        __syncthreads();
    }

    // Epilogue: bias + store
#pragma unroll
    for (int mt = 0; mt < 2; ++mt) {
#pragma unroll
        for (int nt = 0; nt < 8; ++nt) {
            int r0  = bm + wm * 32 + mt * 16 + (lane >> 2);
            int col = bn + wn * 64 + nt * 8 + 2 * (lane & 3);
            float bb0 = bias[col], bb1 = bias[col + 1];
            *(float2*)&C[(size_t)r0 * N + col] =
                make_float2(c[mt][nt][0] + bb0, c[mt][nt][1] + bb1);
            *(float2*)&C[(size_t)(r0 + 8) * N + col] =
                make_float2(c[mt][nt][2] + bb0, c[mt][nt][3] + bb1);
        }
    }
}

// ---------------------------------------------------------------------------
// Fused RMSNorm (over full 1536) + RoPE, in-place. One block per position.
// ---------------------------------------------------------------------------
__global__ __launch_bounds__(256) void rmsnorm_rope_kernel(
    float* __restrict__ X, const float* __restrict__ g)
{
    __shared__ float sh[DIM];
    __shared__ float red[8];
    __shared__ float s_r;

    const int s = blockIdx.x;
    const int t = threadIdx.x;
    float* row = X + (size_t)s * DIM;

    float ss = 0.f;
    for (int i = t; i < DIM; i += 256) {
        float v = row[i];
        sh[i] = v;
        ss += v * v;
    }
#pragma unroll
    for (int off = 16; off > 0; off >>= 1)
        ss += __shfl_xor_sync(0xFFFFFFFFu, ss, off);
    if ((t & 31) == 0) red[t >> 5] = ss;
    __syncthreads();
    if (t == 0) {
        float tot = 0.f;
#pragma unroll
        for (int w = 0; w < 8; w++) tot += red[w];
        s_r = rsqrtf(tot / (float)DIM + EPS);
    }
    __syncthreads();
    const float r = s_r;

    for (int p = t; p < DIM / 2; p += 256) {
        int f0 = 2 * p, f1 = 2 * p + 1;
        int j = p & 63;
        float c  = g_trig[((size_t)s * 64 + j) * 2 + 0];
        float sn = g_trig[((size_t)s * 64 + j) * 2 + 1];
        float v0 = sh[f0] * r * g[f0];
        float v1 = sh[f1] * r * g[f1];
        row[f0] = v0 * c - v1 * sn;
        row[f1] = v0 * sn + v1 * c;
    }
}

// ---------------------------------------------------------------------------
// tf32 tensor-core flash attention.
// 128 threads (4 warps), BQ=64 (16 rows/warp), BK=64, d=128.
// Q fragments persist in registers. K/V/P in smem with per-buffer strides
// chosen for conflict-free fragment access.
// ---------------------------------------------------------------------------
#define KS_STRIDE 132
#define VS_STRIDE 136
#define PS_STRIDE 68
#define FA_SMEM_BYTES ((64 * KS_STRIDE + 64 * VS_STRIDE + 64 * PS_STRIDE) * 4)

__global__ __launch_bounds__(128, 2) void flash_tf32_kernel(
    const float* __restrict__ Q, const float* __restrict__ Kg,
    const float* __restrict__ Vg, float* __restrict__ O)
{
    extern __shared__ float sm[];
    float* Ks = sm;                      // 64 x 132
    float* Vs = Ks + 64 * KS_STRIDE;     // 64 x 136
    float* Ps = Vs + 64 * VS_STRIDE;     // 64 x 68

    const int h    = blockIdx.y;
    const int qb   = blockIdx.x;
    const int t    = threadIdx.x;
    const int lane = t & 31;
    const int warp = t >> 5;
    const int r0   = lane >> 2;   // 0..7
    const int qc   = lane & 3;    // 0..3
    const float scale = 0.08838834764831845f;   // 1/sqrt(128)

    // ---- Stage Q tile into Ks, then pull A-fragments into registers ----
    {
        const float* src = Q + (size_t)(qb * 64) * DIM + h * HDIM;
        for (int i = t; i < 64 * 32; i += 128) {
            int r = i >> 5, c4 = (i & 31) * 4;
            float4 v = *(const float4*)&src[(size_t)r * DIM + c4];
            float* d = &Ks[r * KS_STRIDE + c4];
            d[0] = to_tf32(v.x); d[1] = to_tf32(v.y);
            d[2] = to_tf32(v.z); d[3] = to_tf32(v.w);
        }
    }
    __syncthreads();

    unsigned qa[16][4];
    {
        const int rb = warp * 16 + r0;
#pragma unroll
        for (int kt = 0; kt < 16; ++kt) {
            int kc = kt * 8 + qc;
            qa[kt][0] = fu(Ks[rb * KS_STRIDE + kc]);
            qa[kt][1] = fu(Ks[(rb + 8) * KS_STRIDE + kc]);
            qa[kt][2] = fu(Ks[rb * KS_STRIDE + kc + 4]);
            qa[kt][3] = fu(Ks[(rb + 8) * KS_STRIDE + kc + 4]);
        }
    }
    __syncthreads();

    float o[16][4];
#pragma unroll
    for (int nt = 0; nt < 16; ++nt)
#pragma unroll
        for (int j = 0; j < 4; ++j) o[nt][j] = 0.f;

    float m0 = -1e30f, m1 = -1e30f, l0 = 0.f, l1 = 0.f;
    const int prow = warp * 16 + r0;

    for (int kb = 0; kb < SEQ / 64; ++kb) {
        // ---- Load K and V tiles (cvt to tf32 at store) ----
        const float* ksrc = Kg + (size_t)(kb * 64) * DIM + h * HDIM;
        const float* vsrc = Vg + (size_t)(kb * 64) * DIM + h * HDIM;
        for (int i = t; i < 64 * 32; i += 128) {
            int r = i >> 5, c4 = (i & 31) * 4;
            float4 kv = *(const float4*)&ksrc[(size_t)r * DIM + c4];
            float4 vv = *(const float4*)&vsrc[(size_t)r * DIM + c4];
            float* dk = &Ks[r * KS_STRIDE + c4];
            dk[0] = to_tf32(kv.x); dk[1] = to_tf32(kv.y);
            dk[2] = to_tf32(kv.z); dk[3] = to_tf32(kv.w);
            float* dv = &Vs[r * VS_STRIDE + c4];
            dv[0] = to_tf32(vv.x); dv[1] = to_tf32(vv.y);
            dv[2] = to_tf32(vv.z); dv[3] = to_tf32(vv.w);
        }
        __syncthreads();

        // ---- S = Q @ K^T  (per warp: 16 x 64) ----
        float s[8][4];
#pragma unroll
        for (int nt = 0; nt < 8; ++nt)
#pragma unroll
            for (int j = 0; j < 4; ++j) s[nt][j] = 0.f;

#pragma unroll
        for (int nt = 0; nt < 8; ++nt) {
            const int n = nt * 8 + r0;
#pragma unroll
            for (int kt = 0; kt < 16; ++kt) {
                int kc = kt * 8 + qc;
                unsigned b0 = fu(Ks[n * KS_STRIDE + kc]);
                unsigned b1 = fu(Ks[n * KS_STRIDE + kc + 4]);
                mma_tf32(s[nt], qa[kt], b0, b1);
            }
        }

        // ---- Online softmax (rows r0, r0+8 of this warp) ----
        float mx0 = -1e30f, mx1 = -1e30f;
#pragma unroll
        for (int nt = 0; nt < 8; ++nt) {
            mx0 = fmaxf(mx0, fmaxf(s[nt][0], s[nt][1]));
            mx1 = fmaxf(mx1, fmaxf(s[nt][2], s[nt][3]));
        }
        mx0 = fmaxf(mx0, __shfl_xor_sync(0xFFFFFFFFu, mx0, 1));
        mx0 = fmaxf(mx0, __shfl_xor_sync(0xFFFFFFFFu, mx0, 2));
        mx1 = fmaxf(mx1, __shfl_xor_sync(0xFFFFFFFFu, mx1, 1));
        mx1 = fmaxf(mx1, __shfl_xor_sync(0xFFFFFFFFu, mx1, 2));

        float nm0 = fmaxf(m0, mx0 * scale);
        float nm1 = fmaxf(m1, mx1 * scale);
        float corr0 = __expf(m0 - nm0);
        float corr1 = __expf(m1 - nm1);

        float sum0 = 0.f, sum1 = 0.f;
#pragma unroll
        for (int nt = 0; nt < 8; ++nt) {
            s[nt][0] = __expf(s[nt][0] * scale - nm0);
            s[nt][1] = __expf(s[nt][1] * scale - nm0);
            s[nt][2] = __expf(s[nt][2] * scale - nm1);
            s[nt][3] = __expf(s[nt][3] * scale - nm1);
            sum0 += s[nt][0] + s[nt][1];
            sum1 += s[nt][2] + s[nt][3];
        }
        sum0 += __shfl_xor_sync(0xFFFFFFFFu, sum0, 1);
        sum0 += __shfl_xor_sync(0xFFFFFFFFu, sum0, 2);
        sum1 += __shfl_xor_sync(0xFFFFFFFFu, sum1, 1);
        sum1 += __shfl_xor_sync(0xFFFFFFFFu, sum1, 2);

        l0 = l0 * corr0 + sum0;
        l1 = l1 * corr1 + sum1;
        m0 = nm0;
        m1 = nm1;

#pragma unroll
        for (int nt = 0; nt < 16; ++nt) {
            o[nt][0] *= corr0; o[nt][1] *= corr0;
            o[nt][2] *= corr1; o[nt][3] *= corr1;
        }

        // ---- Store P to smem (warp-local), tf32-rounded ----
#pragma unroll
        for (int nt = 0; nt < 8; ++nt) {
            int pc = nt * 8 + 2 * qc;
            *(float2*)&Ps[prow * PS_STRIDE + pc] =
                make_float2(to_tf32(s[nt][0]), to_tf32(s[nt][1]));
            *(float2*)&Ps[(prow + 8) * PS_STRIDE + pc] =
                make_float2(to_tf32(s[nt][2]), to_tf32(s[nt][3]));
        }
        __syncwarp();

        // ---- O += P @ V ----
#pragma unroll
        for (int kt = 0; kt < 8; ++kt) {
            unsigned a[4];
            int kc = kt * 8 + qc;
            a[0] = fu(Ps[prow * PS_STRIDE + kc]);
            a[1] = fu(Ps[(prow + 8) * PS_STRIDE + kc]);
            a[2] = fu(Ps[prow * PS_STRIDE + kc + 4]);
            a[3] = fu(Ps[(prow + 8) * PS_STRIDE + kc + 4]);
            const int vr = (kt * 8 + qc) * VS_STRIDE + r0;
#pragma unroll
            for (int nt = 0; nt < 16; ++nt) {
                unsigned b0 = fu(Vs[vr + nt * 8]);
                unsigned b1 = fu(Vs[vr + nt * 8 + 4 * VS_STRIDE]);
                mma_tf32(o[nt], a, b0, b1);
            }
        }
        __syncthreads();
    }

    // ---- Epilogue: normalize and store ----
    float inv0 = 1.f / l0, inv1 = 1.f / l1;
    int grow = qb * 64 + warp * 16 + r0;
#pragma unroll
    for (int nt = 0; nt < 16; ++nt) {
        int col = h * HDIM + nt * 8 + 2 * qc;
        *(float2*)&O[(size_t)grow * DIM + col] =
            make_float2(o[nt][0] * inv0, o[nt][1] * inv0);
        *(float2*)&O[(size_t)(grow + 8) * DIM + col] =
            make_float2(o[nt][2] * inv1, o[nt][3] * inv1);
    }
}

// ---------------------------------------------------------------------------
// Launch
// ---------------------------------------------------------------------------
extern "C" void kernel_launch(void* const* d_in, const int* in_sizes, int n_in,
                              void* d_out, int out_size)
{
    const float* x     = (const float*)d_in[0];
    const float* freqs = (const float*)d_in[1];
    const float* Wq    = (const float*)d_in[2];
    const float* bq    = (const float*)d_in[3];
    const float* Wk    = (const float*)d_in[4];
    const float* bk    = (const float*)d_in[5];
    const float* Wv    = (const float*)d_in[6];
    const float* bv    = (const float*)d_in[7];
    const float* Wo    = (const float*)d_in[8];
    const float* bo    = (const float*)d_in[9];
    const float* gq    = (const float*)d_in[10];
    const float* gk    = (const float*)d_in[11];
    float* out = (float*)d_out;

    float *q, *k, *v, *attn;
    cudaGetSymbolAddress((void**)&q,    g_q);
    cudaGetSymbolAddress((void**)&k,    g_k);
    cudaGetSymbolAddress((void**)&v,    g_v);
    cudaGetSymbolAddress((void**)&attn, g_attn);

    cudaFuncSetAttribute(flash_tf32_kernel,
                         cudaFuncAttributeMaxDynamicSharedMemorySize, FA_SMEM_BYTES);

    dim3 gemm_grid(DIM / 128, SEQ / 128);   // (12, 32)

    trig_kernel<<<(SEQ * 64 + 255) / 256, 256>>>(freqs);

    gemm_tf32_kernel<<<gemm_grid, 256>>>(x, Wq, bq, q, SEQ, DIM, DIM);
    gemm_tf32_kernel<<<gemm_grid, 256>>>(x, Wk, bk, k, SEQ, DIM, DIM);
    gemm_tf32_kernel<<<gemm_grid, 256>>>(x, Wv, bv, v, SEQ, DIM, DIM);

    rmsnorm_rope_kernel<<<SEQ, 256>>>(q, gq);
    rmsnorm_rope_kernel<<<SEQ, 256>>>(k, gk);

    flash_tf32_kernel<<<dim3(SEQ / 64, NHEADS), 128, FA_SMEM_BYTES>>>(q, k, v, attn);

    gemm_tf32_kernel<<<gemm_grid, 256>>>(attn, Wo, bo, out, SEQ, DIM, DIM);
}